// round 6
// baseline (speedup 1.0000x reference)
#include <cuda_runtime.h>

// LengthRegulator: out[b,t,:] = x[b, tok(b,t), :] where tok = searchsorted(cumsum(dur), t, 'right')
// Static shapes: B=16, L=512, D=512, T_MAX=4096. Output fp32 [B, T, D].

constexpr int B = 16;
constexpr int L = 512;
constexpr int D = 512;          // 512 floats = 128 float4 per row
constexpr int T = 4096;
constexpr int D4 = D / 4;       // 128 float4 per row

// Scratch token indices: tok[b*T + t], -1 => zero-pad frame. 256 KB device global (no alloc).
__device__ int g_tok[B * T];

// Kernel A: per-batch inclusive scan of durations + binary search per output frame.
__global__ void scan_search_kernel(const int* __restrict__ dur) {
    __shared__ int s[L];
    const int b = blockIdx.x;
    const int tid = threadIdx.x;

    s[tid] = dur[b * L + tid];
    __syncthreads();

    #pragma unroll
    for (int off = 1; off < L; off <<= 1) {
        int v = (tid >= off) ? s[tid - off] : 0;
        __syncthreads();
        s[tid] += v;
        __syncthreads();
    }
    const int total = s[L - 1];

    #pragma unroll
    for (int t = tid; t < T; t += L) {
        int tok;
        if (t >= total) {
            tok = -1;
        } else {
            int lo = 0, hi = L;
            while (lo < hi) {                 // full-convergence upper_bound
                int mid = (lo + hi) >> 1;
                if (s[mid] <= t) lo = mid + 1; else hi = mid;
            }
            tok = lo < (L - 1) ? lo : (L - 1);
        }
        g_tok[b * T + t] = tok;
    }
}

// Kernel B: one warp per output frame (2 KB row). Each thread moves 4 float4 = 64 B.
// tok load is warp-uniform (one broadcast). Streaming stores keep x L2-resident.
__global__ void gather_kernel(const float4* __restrict__ x4, float4* __restrict__ out4) {
    const int tidg = blockIdx.x * blockDim.x + threadIdx.x;   // 2,097,152 threads
    const int fr   = tidg >> 5;            // frame index b*T + t  (65536 frames)
    const int lane = tidg & 31;
    const int b    = fr >> 12;             // / T

    const int tok  = g_tok[fr];            // warp-uniform -> single broadcast load
    const int o    = fr * D4 + lane * 4;   // 64B-aligned slot within output

    if (tok >= 0) {
        const float4* src = x4 + (b * L + tok) * D4 + lane * 4;
        // 4 independent loads (MLP=4), then 4 streaming stores
        float4 v0 = __ldg(src + 0);
        float4 v1 = __ldg(src + 1);
        float4 v2 = __ldg(src + 2);
        float4 v3 = __ldg(src + 3);
        __stcs(out4 + o + 0, v0);
        __stcs(out4 + o + 1, v1);
        __stcs(out4 + o + 2, v2);
        __stcs(out4 + o + 3, v3);
    } else {
        const float4 z = make_float4(0.f, 0.f, 0.f, 0.f);
        __stcs(out4 + o + 0, z);
        __stcs(out4 + o + 1, z);
        __stcs(out4 + o + 2, z);
        __stcs(out4 + o + 3, z);
    }
}

extern "C" void kernel_launch(void* const* d_in, const int* in_sizes, int n_in,
                              void* d_out, int out_size) {
    const float* x   = (const float*)d_in[0];
    const int*   dur = (const int*)d_in[1];
    // d_in[2] = mel_max_length (static 4096, baked into constants)

    scan_search_kernel<<<B, L>>>(dur);

    const int total_threads = B * T * 32;      // one warp per frame
    const int threads = 256;
    gather_kernel<<<total_threads / threads, threads>>>((const float4*)x, (float4*)d_out);

    (void)in_sizes; (void)n_in; (void)out_size;
}

// round 7
// speedup vs baseline: 2.4694x; 2.4694x over previous
#include <cuda_runtime.h>

// LengthRegulator: out[b,t,:] = x[b, tok(b,t), :] where tok = searchsorted(cumsum(dur), t, 'right')
// Static shapes: B=16, L=512, D=512, T_MAX=4096. Output fp32 [B, T, D].

constexpr int B = 16;
constexpr int L = 512;
constexpr int D = 512;          // 512 floats = 128 float4 per row
constexpr int T = 4096;
constexpr int D4 = D / 4;       // 128 float4 per row

// Scratch token indices: tok[b*T + t], -1 => zero-pad frame. 256 KB device global (no alloc).
__device__ int g_tok[B * T];

// Kernel A: per-batch inclusive scan of durations + binary search per output frame.
__global__ void scan_search_kernel(const int* __restrict__ dur) {
    __shared__ int s[L];
    const int b = blockIdx.x;
    const int tid = threadIdx.x;

    s[tid] = dur[b * L + tid];
    __syncthreads();

    #pragma unroll
    for (int off = 1; off < L; off <<= 1) {
        int v = (tid >= off) ? s[tid - off] : 0;
        __syncthreads();
        s[tid] += v;
        __syncthreads();
    }
    const int total = s[L - 1];

    #pragma unroll
    for (int t = tid; t < T; t += L) {
        int tok;
        if (t >= total) {
            tok = -1;
        } else {
            int lo = 0, hi = L;
            while (lo < hi) {                 // full-convergence upper_bound
                int mid = (lo + hi) >> 1;
                if (s[mid] <= t) lo = mid + 1; else hi = mid;
            }
            tok = lo < (L - 1) ? lo : (L - 1);
        }
        g_tok[b * T + t] = tok;
    }
}

// Kernel B: one warp per output frame (2 KB row). Each thread moves 4 float4 = 64 B,
// WARP-STRIDED so every LDG/STG.128 is fully coalesced (32 contiguous float4 = 512 B).
// tok load is warp-uniform (one broadcast). Streaming stores keep x L2-resident.
__global__ void gather_kernel(const float4* __restrict__ x4, float4* __restrict__ out4) {
    const int tidg = blockIdx.x * blockDim.x + threadIdx.x;   // 2,097,152 threads
    const int fr   = tidg >> 5;            // frame index b*T + t  (65536 frames)
    const int lane = tidg & 31;
    const int b    = fr >> 12;             // / T

    const int tok  = g_tok[fr];            // warp-uniform -> single broadcast load

    if (tok >= 0) {
        const float4* src = x4  + (b * L + tok) * D4 + lane;
        float4*       dst = out4 + fr * D4 + lane;
        // 4 independent, fully-coalesced loads (MLP=4), then 4 streaming stores
        float4 v0 = __ldg(src +  0);
        float4 v1 = __ldg(src + 32);
        float4 v2 = __ldg(src + 64);
        float4 v3 = __ldg(src + 96);
        __stcs(dst +  0, v0);
        __stcs(dst + 32, v1);
        __stcs(dst + 64, v2);
        __stcs(dst + 96, v3);
    } else {
        float4* dst = out4 + fr * D4 + lane;
        const float4 z = make_float4(0.f, 0.f, 0.f, 0.f);
        __stcs(dst +  0, z);
        __stcs(dst + 32, z);
        __stcs(dst + 64, z);
        __stcs(dst + 96, z);
    }
}

extern "C" void kernel_launch(void* const* d_in, const int* in_sizes, int n_in,
                              void* d_out, int out_size) {
    const float* x   = (const float*)d_in[0];
    const int*   dur = (const int*)d_in[1];
    // d_in[2] = mel_max_length (static 4096, baked into constants)

    scan_search_kernel<<<B, L>>>(dur);

    const int total_threads = B * T * 32;      // one warp per frame
    const int threads = 256;
    gather_kernel<<<total_threads / threads, threads>>>((const float4*)x, (float4*)d_out);

    (void)in_sizes; (void)n_in; (void)out_size;
}